// round 4
// baseline (speedup 1.0000x reference)
#include <cuda_runtime.h>
#include <math.h>

#define NBLK 128
#define BT_LL  32768LL          // B*T
#define BTV_LL 16777216LL       // B*T*V

// ---------------- scratch (static device globals; no allocation) -------------
__device__ float g_h_enc[786432];    // 3 layers x 2 parity x [128,1024]
__device__ float g_c_enc[393216];    // 3 layers x [128,1024]
__device__ float g_h_dec[786432];
__device__ float g_c_dec[393216];
__device__ float g_z[524288];        // [128,4096] gate pre-activations
__device__ float g_lat[32768];       // [128,256]
__device__ float g_y[33554432];      // [128,256,1024] decoder top-layer h
__device__ float g_logits[16777216]; // [128,256,512]
__device__ unsigned g_bar_count;     // zero-initialized at module load
__device__ unsigned g_bar_phase;

struct Params {
    const int* tokens; const float* emb;
    const float* Wx[6]; const float* Wh[6]; const float* b[6]; // 0..2 enc, 3..5 dec
    const float* w_mean; const float* b_mean;
    const float* w_sigma; const float* b_sigma;
    const float* eps;
};

__device__ __forceinline__ float4 ldf4(const float* p) {
    return *reinterpret_cast<const float4*>(p);
}
__device__ __forceinline__ float4 ldcg4(const float* p) {
    float4 v;
    asm volatile("ld.global.cg.v4.f32 {%0,%1,%2,%3},[%4];"
                 : "=f"(v.x), "=f"(v.y), "=f"(v.z), "=f"(v.w)
                 : "l"(p) : "memory");
    return v;
}
__device__ __forceinline__ float ldcg1(const float* p) {
    float v;
    asm volatile("ld.global.cg.f32 %0,[%1];" : "=f"(v) : "l"(p) : "memory");
    return v;
}
__device__ __forceinline__ unsigned atom_add_acqrel(unsigned* p, unsigned v) {
    unsigned old;
    asm volatile("atom.add.acq_rel.gpu.global.u32 %0,[%1],%2;"
                 : "=r"(old) : "l"(p), "r"(v) : "memory");
    return old;
}
__device__ __forceinline__ void atom_add_release(unsigned* p, unsigned v) {
    unsigned old;
    asm volatile("atom.add.release.gpu.global.u32 %0,[%1],%2;"
                 : "=r"(old) : "l"(p), "r"(v) : "memory");
}
__device__ __forceinline__ unsigned ld_acquire(const unsigned* p) {
    unsigned v;
    asm volatile("ld.acquire.gpu.global.u32 %0,[%1];"
                 : "=r"(v) : "l"(p) : "memory");
    return v;
}
__device__ __forceinline__ void st_relaxed(unsigned* p, unsigned v) {
    asm volatile("st.relaxed.gpu.global.u32 [%0],%1;"
                 :: "l"(p), "r"(v) : "memory");
}

// Grid barrier: 128 blocks, guaranteed co-resident (grid <= SM count, so even
// 1-block/SM occupancy suffices). Acq/rel semantics throughout:
//   arrival = atom.add.acq_rel (release own writes, acquire others' on last),
//   publish = st.relaxed count=0, then atom.add.release phase,
//   spin    = ld.acquire phase.
__device__ __forceinline__ void grid_barrier() {
    __syncthreads();
    if (threadIdx.x == 0) {
        unsigned gen = ld_acquire(&g_bar_phase);
        unsigned old = atom_add_acqrel(&g_bar_count, 1u);
        if (old == NBLK - 1u) {
            st_relaxed(&g_bar_count, 0u);
            atom_add_release(&g_bar_phase, 1u);
        } else {
            while (ld_acquire(&g_bar_phase) == gen) {}
        }
    }
    __syncthreads();
}

// A-operand fetch: 4 consecutive floats at logical column gk of A=[A1|A2], row gm.
//   mode 0: A1 dense [128,1024]  (prev layer h, current parity)
//   mode 1: A1 = emb[tokens[gm,t], :]             (K1=512)
//   mode 2: A1 = [g_lat[gm,:] (256) | emb-gather]  (K1=768)
// A2 = this layer's h, previous-step parity, [128,1024].
__device__ __forceinline__ float4 fetchA(
    int mode, int K1, const float* A1, const float* A2,
    const int* __restrict__ tokens, int t, const float* __restrict__ emb,
    int gm, int gk)
{
    if (gk >= K1) return ldcg4(A2 + gm * 1024 + (gk - K1));
    if (mode == 0) return ldcg4(A1 + gm * 1024 + gk);
    if (mode == 1) {
        int tok = __ldg(&tokens[gm * 256 + t]);
        return ldf4(emb + (size_t)tok * 512 + gk);
    }
    if (gk < 256) return ldcg4(g_lat + gm * 256 + gk);
    int tok = __ldg(&tokens[gm * 256 + t]);
    return ldf4(emb + (size_t)tok * 512 + (gk - 256));
}

// GEMM phase of one LSTM layer step: z = [A1|A2] @ [Wx;Wh] -> Z[128,4096].
// Plain 64x64 tile, direct z columns (no gate interleave). 256 threads,
// 4x4 outputs each. grid: bid -> bn = bid&63 (col tile), bm = bid>>6 (row tile).
__device__ void gemm_step(
    float (*As)[68], float (*Bs)[64], int bid, int mode, int K1,
    const float* __restrict__ Wx, const float* __restrict__ Wh,
    const float* A1, const float* A2, float* __restrict__ Z,
    int t, const int* __restrict__ tokens, const float* __restrict__ emb)
{
    const int tid = threadIdx.x;
    const int bn = bid & 63, bm = bid >> 6;
    const int row0 = bm * 64, col0 = bn * 64;
    const int KT = K1 + 1024;
    const int tx = tid & 15, ty = tid >> 4;      // cols col0+tx*4, rows row0+ty*4
    const int mA = tid >> 2, kqA = (tid & 3) * 4; // A-tile chunk
    const int kkB = tid >> 4, nqB = tid & 15;     // B-tile chunk

    float acc[4][4];
#pragma unroll
    for (int r = 0; r < 4; r++)
#pragma unroll
        for (int c2 = 0; c2 < 4; c2++) acc[r][c2] = 0.0f;

    float4 pa, pb;
    // prefetch + store k-tile 0
    pa = fetchA(mode, K1, A1, A2, tokens, t, emb, row0 + mA, kqA);
    pb = ldf4(((kkB < K1) ? Wx + (size_t)kkB * 4096
                          : Wh + (size_t)(kkB - K1) * 4096) + col0 + nqB * 4);
    As[kqA + 0][mA] = pa.x; As[kqA + 1][mA] = pa.y;
    As[kqA + 2][mA] = pa.z; As[kqA + 3][mA] = pa.w;
    *reinterpret_cast<float4*>(&Bs[kkB][nqB * 4]) = pb;
    __syncthreads();

    for (int k0 = 16;; k0 += 16) {
        const bool more = (k0 < KT);
        if (more) {
            pa = fetchA(mode, K1, A1, A2, tokens, t, emb, row0 + mA, k0 + kqA);
            int gk = k0 + kkB;
            pb = ldf4(((gk < K1) ? Wx + (size_t)gk * 4096
                                 : Wh + (size_t)(gk - K1) * 4096) + col0 + nqB * 4);
        }
#pragma unroll
        for (int kk = 0; kk < 16; kk++) {
            float4 a = ldf4(&As[kk][ty * 4]);
            float4 b = ldf4(&Bs[kk][tx * 4]);
            float av[4] = {a.x, a.y, a.z, a.w};
            float bv[4] = {b.x, b.y, b.z, b.w};
#pragma unroll
            for (int r = 0; r < 4; r++)
#pragma unroll
                for (int c2 = 0; c2 < 4; c2++)
                    acc[r][c2] = fmaf(av[r], bv[c2], acc[r][c2]);
        }
        if (!more) break;
        __syncthreads();
        As[kqA + 0][mA] = pa.x; As[kqA + 1][mA] = pa.y;
        As[kqA + 2][mA] = pa.z; As[kqA + 3][mA] = pa.w;
        *reinterpret_cast<float4*>(&Bs[kkB][nqB * 4]) = pb;
        __syncthreads();
    }

#pragma unroll
    for (int r = 0; r < 4; r++) {
        float4 v = make_float4(acc[r][0], acc[r][1], acc[r][2], acc[r][3]);
        *reinterpret_cast<float4*>(
            Z + (size_t)(row0 + ty * 4 + r) * 4096 + col0 + tx * 4) = v;
    }
}

// Cell phase. Flat 1:1 thread->element mapping (gid0 in [0,32768), 4 elems per
// thread), so each c element is touched by exactly one thread every step.
__device__ __forceinline__ void cell_step(
    int gid0, const float* __restrict__ Z,
    float* __restrict__ h, float* __restrict__ c,
    const float* __restrict__ bias, float* __restrict__ y, int t)
{
#pragma unroll
    for (int it = 0; it < 4; it++) {
        int idx = gid0 + it * 32768;
        int b = idx >> 10, u = idx & 1023;
        const float* zr = Z + (size_t)b * 4096;
        float zi = ldcg1(zr + u)        + __ldg(&bias[u]);
        float zf = ldcg1(zr + 1024 + u) + __ldg(&bias[1024 + u]);
        float zg = ldcg1(zr + 2048 + u) + __ldg(&bias[2048 + u]);
        float zo = ldcg1(zr + 3072 + u) + __ldg(&bias[3072 + u]);
        float si = 1.0f / (1.0f + expf(-zi));
        float sf = 1.0f / (1.0f + expf(-zf));
        float so = 1.0f / (1.0f + expf(-zo));
        float cc = sf * c[idx] + si * tanhf(zg);
        c[idx] = cc;
        float hh = so * tanhf(cc);
        h[idx] = hh;
        if (y) y[((size_t)b * 256 + t) * 1024 + u] = hh;
    }
}

// Persistent kernel: full encoder scan + latent + decoder scan.
// 128 blocks <= SM count -> all blocks co-resident unconditionally.
__global__ void __launch_bounds__(256) vae_persistent(Params p)
{
    __shared__ float As[16][68];
    __shared__ float Bs[16][64];
    __shared__ float s_c3[1024];

    const int bid = blockIdx.x;
    const int tid = threadIdx.x;
    const int gid0 = bid * 256 + tid;   // 0..32767

    // zero all recurrent state
    for (int i = gid0; i < 786432; i += NBLK * 256) {
        g_h_enc[i] = 0.0f; g_h_dec[i] = 0.0f;
    }
    for (int i = gid0; i < 393216; i += NBLK * 256) {
        g_c_enc[i] = 0.0f; g_c_dec[i] = 0.0f;
    }
    grid_barrier();

    // ------------- encoder -------------
    for (int t = 0; t < 256; t++) {
        const int pw = t & 1, pr = pw ^ 1;
        gemm_step(As, Bs, bid, 1, 512, p.Wx[0], p.Wh[0],
                  nullptr, g_h_enc + pr * 131072, g_z, t, p.tokens, p.emb);
        grid_barrier();
        cell_step(gid0, g_z, g_h_enc + pw * 131072, g_c_enc, p.b[0], nullptr, t);
        grid_barrier();
        gemm_step(As, Bs, bid, 0, 1024, p.Wx[1], p.Wh[1],
                  g_h_enc + pw * 131072, g_h_enc + (2 + pr) * 131072,
                  g_z, t, p.tokens, p.emb);
        grid_barrier();
        cell_step(gid0, g_z, g_h_enc + (2 + pw) * 131072, g_c_enc + 131072,
                  p.b[1], nullptr, t);
        grid_barrier();
        gemm_step(As, Bs, bid, 0, 1024, p.Wx[2], p.Wh[2],
                  g_h_enc + (2 + pw) * 131072, g_h_enc + (4 + pr) * 131072,
                  g_z, t, p.tokens, p.emb);
        grid_barrier();
        cell_step(gid0, g_z, g_h_enc + (4 + pw) * 131072, g_c_enc + 262144,
                  p.b[2], nullptr, t);
        grid_barrier();
    }

    // ------------- latent: projects CELL state c3; eps ADDED (faithful) -----
    {
        const int row = bid;               // 128 blocks = 128 batch rows
        const float* c3 = g_c_enc + 262144 + row * 1024;
        for (int i = tid; i < 1024; i += 256) s_c3[i] = ldcg1(c3 + i);
        __syncthreads();
        const int col = tid;               // 256 threads = 256 latent cols
        float am = 0.0f, as = 0.0f;
        for (int k = 0; k < 1024; k++) {
            float a = s_c3[k];
            am = fmaf(a, __ldg(&p.w_mean[k * 256 + col]), am);
            as = fmaf(a, __ldg(&p.w_sigma[k * 256 + col]), as);
        }
        float mean = am + __ldg(&p.b_mean[col]);
        float sg   = as + __ldg(&p.b_sigma[col]);
        g_lat[row * 256 + col] = mean + expf(0.5f * sg)
                               + __ldg(&p.eps[row * 256 + col]);
        __syncthreads();
    }
    grid_barrier();

    // ------------- decoder -------------
    for (int t = 0; t < 256; t++) {
        const int pw = t & 1, pr = pw ^ 1;
        gemm_step(As, Bs, bid, 2, 768, p.Wx[3], p.Wh[3],
                  nullptr, g_h_dec + pr * 131072, g_z, t, p.tokens, p.emb);
        grid_barrier();
        cell_step(gid0, g_z, g_h_dec + pw * 131072, g_c_dec, p.b[3], nullptr, t);
        grid_barrier();
        gemm_step(As, Bs, bid, 0, 1024, p.Wx[4], p.Wh[4],
                  g_h_dec + pw * 131072, g_h_dec + (2 + pr) * 131072,
                  g_z, t, p.tokens, p.emb);
        grid_barrier();
        cell_step(gid0, g_z, g_h_dec + (2 + pw) * 131072, g_c_dec + 131072,
                  p.b[4], nullptr, t);
        grid_barrier();
        gemm_step(As, Bs, bid, 0, 1024, p.Wx[5], p.Wh[5],
                  g_h_dec + (2 + pw) * 131072, g_h_dec + (4 + pr) * 131072,
                  g_z, t, p.tokens, p.emb);
        grid_barrier();
        cell_step(gid0, g_z, g_h_dec + (4 + pw) * 131072, g_c_dec + 262144,
                  p.b[5], g_y, t);
        grid_barrier();
    }
}

// Dense logits GEMM: Z[32768,512] = Y[32768,1024] @ W[1024,512] + b.
__global__ void __launch_bounds__(128) logits_gemm(
    const float* __restrict__ A, const float* __restrict__ W,
    const float* __restrict__ bias, float* __restrict__ Z)
{
    __shared__ float As[16][68];
    __shared__ float Bs[16][64];
    const int tid = threadIdx.x;
    const int tx = tid & 15, ty = tid >> 4;
    const int row0 = blockIdx.y * 64, col0 = blockIdx.x * 64;

    float4 pa[2], pb[2];
#pragma unroll
    for (int j = 0; j < 2; j++) {
        int c = tid + j * 128;
        pa[j] = ldf4(A + (size_t)(row0 + (c >> 2)) * 1024 + (c & 3) * 4);
        int kk = c >> 4, nq = c & 15;
        pb[j] = ldf4(W + (size_t)kk * 512 + col0 + nq * 4);
    }
#pragma unroll
    for (int j = 0; j < 2; j++) {
        int c = tid + j * 128;
        int m = c >> 2, kb = (c & 3) * 4;
        As[kb + 0][m] = pa[j].x; As[kb + 1][m] = pa[j].y;
        As[kb + 2][m] = pa[j].z; As[kb + 3][m] = pa[j].w;
        int kk = c >> 4, nq = c & 15;
        *reinterpret_cast<float4*>(&Bs[kk][nq * 4]) = pb[j];
    }
    __syncthreads();

    float acc[8][4];
#pragma unroll
    for (int r = 0; r < 8; r++)
#pragma unroll
        for (int c2 = 0; c2 < 4; c2++) acc[r][c2] = 0.0f;

    for (int k0 = 16;; k0 += 16) {
        const bool more = (k0 < 1024);
        if (more) {
#pragma unroll
            for (int j = 0; j < 2; j++) {
                int c = tid + j * 128;
                pa[j] = ldf4(A + (size_t)(row0 + (c >> 2)) * 1024 + k0 + (c & 3) * 4);
                int kk = c >> 4, nq = c & 15;
                pb[j] = ldf4(W + (size_t)(k0 + kk) * 512 + col0 + nq * 4);
            }
        }
#pragma unroll
        for (int kk = 0; kk < 16; kk++) {
            float4 a0 = ldf4(&As[kk][ty * 8]);
            float4 a1 = ldf4(&As[kk][ty * 8 + 4]);
            float4 b  = ldf4(&Bs[kk][tx * 4]);
            float av[8] = {a0.x, a0.y, a0.z, a0.w, a1.x, a1.y, a1.z, a1.w};
            float bv[4] = {b.x, b.y, b.z, b.w};
#pragma unroll
            for (int r = 0; r < 8; r++)
#pragma unroll
                for (int c2 = 0; c2 < 4; c2++)
                    acc[r][c2] = fmaf(av[r], bv[c2], acc[r][c2]);
        }
        if (!more) break;
        __syncthreads();
#pragma unroll
        for (int j = 0; j < 2; j++) {
            int c = tid + j * 128;
            int m = c >> 2, kb = (c & 3) * 4;
            As[kb + 0][m] = pa[j].x; As[kb + 1][m] = pa[j].y;
            As[kb + 2][m] = pa[j].z; As[kb + 3][m] = pa[j].w;
            int kk = c >> 4, nq = c & 15;
            *reinterpret_cast<float4*>(&Bs[kk][nq * 4]) = pb[j];
        }
        __syncthreads();
    }

    float4 bv4 = ldf4(bias + col0 + tx * 4);
#pragma unroll
    for (int r = 0; r < 8; r++) {
        float4 v = make_float4(acc[r][0] + bv4.x, acc[r][1] + bv4.y,
                               acc[r][2] + bv4.z, acc[r][3] + bv4.w);
        *reinterpret_cast<float4*>(
            Z + (size_t)(row0 + ty * 8 + r) * 512 + col0 + tx * 4) = v;
    }
}

// argmax (first-occurrence tie-break, like jnp.argmax) + logits emission.
__global__ void emit_kernel(const float* __restrict__ logits,
                            float* __restrict__ out, long long out_size)
{
    int row = blockIdx.x;
    int tid = threadIdx.x;
    const float* lr = logits + (size_t)row * 512;

    float best = -3.402823466e38f; int bi = 0;
#pragma unroll
    for (int j = 0; j < 4; j++) {
        int vi = tid + j * 128;
        float v = lr[vi];
        if (v > best) { best = v; bi = vi; }
    }
    __shared__ float sv[128]; __shared__ int si[128];
    sv[tid] = best; si[tid] = bi;
    __syncthreads();
    for (int s = 64; s > 0; s >>= 1) {
        if (tid < s) {
            float v2 = sv[tid + s]; int i2 = si[tid + s];
            if (v2 > sv[tid] || (v2 == sv[tid] && i2 < si[tid])) {
                sv[tid] = v2; si[tid] = i2;
            }
        }
        __syncthreads();
    }
    int amax = si[0];

    if (out_size == BT_LL + BTV_LL) {
        if (tid == 0) out[row] = (float)amax;
        float* lo = out + BT_LL + (size_t)row * 512;
#pragma unroll
        for (int j = 0; j < 4; j++) lo[tid + j * 128] = lr[tid + j * 128];
    } else if (out_size == BTV_LL) {
        float* lo = out + (size_t)row * 512;
#pragma unroll
        for (int j = 0; j < 4; j++) lo[tid + j * 128] = lr[tid + j * 128];
    } else if (out_size == BT_LL) {
        if (tid == 0) reinterpret_cast<int*>(out)[row] = amax;
    } else {
        if (tid == 0 && (long long)row < out_size) out[row] = (float)amax;
#pragma unroll
        for (int j = 0; j < 4; j++) {
            long long o = BT_LL + (long long)row * 512 + tid + j * 128;
            if (o < out_size) out[o] = lr[tid + j * 128];
        }
    }
}

extern "C" void kernel_launch(void* const* d_in, const int* in_sizes, int n_in,
                              void* d_out, int out_size)
{
    Params p;
    p.tokens = (const int*)d_in[0];
    p.emb    = (const float*)d_in[1];
    p.Wx[0] = (const float*)d_in[2];  p.Wh[0] = (const float*)d_in[3];  p.b[0] = (const float*)d_in[4];
    p.Wx[1] = (const float*)d_in[5];  p.Wh[1] = (const float*)d_in[6];  p.b[1] = (const float*)d_in[7];
    p.Wx[2] = (const float*)d_in[8];  p.Wh[2] = (const float*)d_in[9];  p.b[2] = (const float*)d_in[10];
    p.Wx[3] = (const float*)d_in[11]; p.Wh[3] = (const float*)d_in[12]; p.b[3] = (const float*)d_in[13];
    p.Wx[4] = (const float*)d_in[14]; p.Wh[4] = (const float*)d_in[15]; p.b[4] = (const float*)d_in[16];
    p.Wx[5] = (const float*)d_in[17]; p.Wh[5] = (const float*)d_in[18]; p.b[5] = (const float*)d_in[19];
    p.w_mean  = (const float*)d_in[20];
    p.b_mean  = (const float*)d_in[21];
    p.w_sigma = (const float*)d_in[22];
    p.b_sigma = (const float*)d_in[23];
    const float* dec_w = (const float*)d_in[24];
    const float* dec_b = (const float*)d_in[25];
    p.eps = (const float*)d_in[26];

    float *y, *lg;
    cudaGetSymbolAddress((void**)&y,  g_y);
    cudaGetSymbolAddress((void**)&lg, g_logits);

    vae_persistent<<<NBLK, 256>>>(p);
    logits_gemm<<<dim3(8, 512), 128>>>(y, dec_w, dec_b, lg);
    emit_kernel<<<32768, 128>>>(lg, (float*)d_out, (long long)out_size);
}

// round 5
// speedup vs baseline: 1.5695x; 1.5695x over previous
#include <cuda_runtime.h>
#include <math.h>

#define NBLK 256
#define BT_LL  32768LL          // B*T
#define BTV_LL 16777216LL       // B*T*V

// ---------------- scratch (static device globals; no allocation) -------------
__device__ float g_h_enc[786432];    // 3 layers x 2 parity x [128,1024]
__device__ float g_c_enc[393216];    // 3 layers x [128,1024]
__device__ float g_h_dec[786432];
__device__ float g_c_dec[393216];
__device__ float g_z[1048576];       // 2 K-partials x [128,4096]
__device__ float g_lat[32768];       // [128,256]
__device__ float g_y[33554432];      // [128,256,1024] decoder top-layer h
__device__ float g_logits[16777216]; // [128,256,512]
__device__ unsigned g_bar_count;     // zero-initialized at module load
__device__ unsigned g_bar_phase;

struct Params {
    const int* tokens; const float* emb;
    const float* Wx[6]; const float* Wh[6]; const float* b[6]; // 0..2 enc, 3..5 dec
    const float* w_mean; const float* b_mean;
    const float* w_sigma; const float* b_sigma;
    const float* eps;
};

__device__ __forceinline__ float4 ldf4(const float* p) {
    return *reinterpret_cast<const float4*>(p);
}
__device__ __forceinline__ float4 ldcg4(const float* p) {
    float4 v;
    asm volatile("ld.global.cg.v4.f32 {%0,%1,%2,%3},[%4];"
                 : "=f"(v.x), "=f"(v.y), "=f"(v.z), "=f"(v.w)
                 : "l"(p) : "memory");
    return v;
}
__device__ __forceinline__ float ldcg1(const float* p) {
    float v;
    asm volatile("ld.global.cg.f32 %0,[%1];" : "=f"(v) : "l"(p) : "memory");
    return v;
}
__device__ __forceinline__ unsigned atom_add_acqrel(unsigned* p, unsigned v) {
    unsigned old;
    asm volatile("atom.add.acq_rel.gpu.global.u32 %0,[%1],%2;"
                 : "=r"(old) : "l"(p), "r"(v) : "memory");
    return old;
}
__device__ __forceinline__ void atom_add_release(unsigned* p, unsigned v) {
    unsigned old;
    asm volatile("atom.add.release.gpu.global.u32 %0,[%1],%2;"
                 : "=r"(old) : "l"(p), "r"(v) : "memory");
}
__device__ __forceinline__ unsigned ld_acquire(const unsigned* p) {
    unsigned v;
    asm volatile("ld.acquire.gpu.global.u32 %0,[%1];"
                 : "=r"(v) : "l"(p) : "memory");
    return v;
}
__device__ __forceinline__ void st_relaxed(unsigned* p, unsigned v) {
    asm volatile("st.relaxed.gpu.global.u32 [%0],%1;"
                 :: "l"(p), "r"(v) : "memory");
}

// Grid barrier (validated in R4, unchanged semantics). 256 blocks co-resident
// by construction: launch_bounds(256,2) -> regs<=128, smem 33.8KB/block ->
// occupancy >= 2 blocks/SM -> 256 <= 2*148.
__device__ __forceinline__ void grid_barrier() {
    __syncthreads();
    if (threadIdx.x == 0) {
        unsigned gen = ld_acquire(&g_bar_phase);
        unsigned old = atom_add_acqrel(&g_bar_count, 1u);
        if (old == NBLK - 1u) {
            st_relaxed(&g_bar_count, 0u);
            atom_add_release(&g_bar_phase, 1u);
        } else {
            while (ld_acquire(&g_bar_phase) == gen) {}
        }
    }
    __syncthreads();
}

// A-operand fetch (validated in R4): 4 floats at logical col gk of A=[A1|A2].
//   mode 0: A1 dense [128,1024];  mode 1: A1 = emb[tokens[gm,t],:] (K1=512)
//   mode 2: A1 = [g_lat[gm,:] | emb-gather] (K1=768).  A2 = prev-parity h.
__device__ __forceinline__ float4 fetchA(
    int mode, int K1, const float* A1, const float* A2,
    const int* __restrict__ tokens, int t, const float* __restrict__ emb,
    int gm, int gk)
{
    if (gk >= K1) return ldcg4(A2 + gm * 1024 + (gk - K1));
    if (mode == 0) return ldcg4(A1 + gm * 1024 + gk);
    if (mode == 1) {
        int tok = __ldg(&tokens[gm * 256 + t]);
        return ldf4(emb + (size_t)tok * 512 + gk);
    }
    if (gk < 256) return ldcg4(g_lat + gm * 256 + gk);
    int tok = __ldg(&tokens[gm * 256 + t]);
    return ldf4(emb + (size_t)tok * 512 + (gk - 256));
}

// Split-K GEMM phase: 256 blocks; block bid computes 64x64 tile
// (bm=(bid&127)>>6, bn=bid&63) over K-half part=bid>>7, writing
// z_part[part] = [A1|A2][:, khalf] @ W[khalf, :]. BK=32, double-buffered smem,
// one __syncthreads per k-tile. 256 threads, 4x4 outputs each.
__device__ void gemm_step(
    float* sA, float* sB, int bid, int mode, int K1, int KT,
    const float* __restrict__ Wx, const float* __restrict__ Wh,
    const float* A1, const float* A2, float* __restrict__ Z,
    int t, const int* __restrict__ tokens, const float* __restrict__ emb)
{
    const int tid = threadIdx.x;
    const int part = bid >> 7;
    const int tb = bid & 127;
    const int bn = tb & 63, bm = tb >> 6;
    const int row0 = bm * 64, col0 = bn * 64;
    const int kh = KT >> 1;               // 768 / 1024 / 896 (all /32)
    const int kbase = part * kh;
    Z += part * 524288;

    const int tx = tid & 15, ty = tid >> 4;
    const int mA  = tid >> 3;             // 0..31 (chunk1 adds +32)
    const int kqA = (tid & 7) * 4;        // 0,4,...,28
    const int kkB = tid >> 4;             // 0..15 (chunk1 adds +16)
    const int nqB = tid & 15;

    float4 a0, a1, b0, b1;

    // prefetch k-tile at kbase
    a0 = fetchA(mode, K1, A1, A2, tokens, t, emb, row0 + mA,      kbase + kqA);
    a1 = fetchA(mode, K1, A1, A2, tokens, t, emb, row0 + mA + 32, kbase + kqA);
    {
        int gk0 = kbase + kkB;
        b0 = ldf4(((gk0 < K1) ? Wx + (size_t)gk0 * 4096
                              : Wh + (size_t)(gk0 - K1) * 4096) + col0 + nqB * 4);
        int gk1 = gk0 + 16;
        b1 = ldf4(((gk1 < K1) ? Wx + (size_t)gk1 * 4096
                              : Wh + (size_t)(gk1 - K1) * 4096) + col0 + nqB * 4);
    }
    // store into buffer 0
    {
        float* pa = sA;                   // buf 0
        pa[(kqA + 0) * 68 + mA] = a0.x; pa[(kqA + 1) * 68 + mA] = a0.y;
        pa[(kqA + 2) * 68 + mA] = a0.z; pa[(kqA + 3) * 68 + mA] = a0.w;
        pa[(kqA + 0) * 68 + mA + 32] = a1.x; pa[(kqA + 1) * 68 + mA + 32] = a1.y;
        pa[(kqA + 2) * 68 + mA + 32] = a1.z; pa[(kqA + 3) * 68 + mA + 32] = a1.w;
        float* pb = sB;
        *reinterpret_cast<float4*>(pb + kkB * 64 + nqB * 4) = b0;
        *reinterpret_cast<float4*>(pb + (kkB + 16) * 64 + nqB * 4) = b1;
    }
    __syncthreads();

    float acc[4][4];
#pragma unroll
    for (int r = 0; r < 4; r++)
#pragma unroll
        for (int c2 = 0; c2 < 4; c2++) acc[r][c2] = 0.0f;

    const int nt = kh >> 5;
    for (int it = 0; it < nt; it++) {
        const int cur = it & 1;
        const bool more = (it + 1 < nt);
        if (more) {
            const int k0 = kbase + (it + 1) * 32;
            a0 = fetchA(mode, K1, A1, A2, tokens, t, emb, row0 + mA,      k0 + kqA);
            a1 = fetchA(mode, K1, A1, A2, tokens, t, emb, row0 + mA + 32, k0 + kqA);
            int gk0 = k0 + kkB;
            b0 = ldf4(((gk0 < K1) ? Wx + (size_t)gk0 * 4096
                                  : Wh + (size_t)(gk0 - K1) * 4096) + col0 + nqB * 4);
            int gk1 = gk0 + 16;
            b1 = ldf4(((gk1 < K1) ? Wx + (size_t)gk1 * 4096
                                  : Wh + (size_t)(gk1 - K1) * 4096) + col0 + nqB * 4);
        }
        const float* pa = sA + cur * 2176;
        const float* pb = sB + cur * 2048;
#pragma unroll
        for (int kk = 0; kk < 32; kk++) {
            float4 av4 = ldf4(pa + kk * 68 + ty * 4);
            float4 bv4 = ldf4(pb + kk * 64 + tx * 4);
            float av[4] = {av4.x, av4.y, av4.z, av4.w};
            float bv[4] = {bv4.x, bv4.y, bv4.z, bv4.w};
#pragma unroll
            for (int r = 0; r < 4; r++)
#pragma unroll
                for (int c2 = 0; c2 < 4; c2++)
                    acc[r][c2] = fmaf(av[r], bv[c2], acc[r][c2]);
        }
        if (more) {
            float* pa2 = sA + (cur ^ 1) * 2176;
            pa2[(kqA + 0) * 68 + mA] = a0.x; pa2[(kqA + 1) * 68 + mA] = a0.y;
            pa2[(kqA + 2) * 68 + mA] = a0.z; pa2[(kqA + 3) * 68 + mA] = a0.w;
            pa2[(kqA + 0) * 68 + mA + 32] = a1.x; pa2[(kqA + 1) * 68 + mA + 32] = a1.y;
            pa2[(kqA + 2) * 68 + mA + 32] = a1.z; pa2[(kqA + 3) * 68 + mA + 32] = a1.w;
            float* pb2 = sB + (cur ^ 1) * 2048;
            *reinterpret_cast<float4*>(pb2 + kkB * 64 + nqB * 4) = b0;
            *reinterpret_cast<float4*>(pb2 + (kkB + 16) * 64 + nqB * 4) = b1;
        }
        __syncthreads();
    }

#pragma unroll
    for (int r = 0; r < 4; r++) {
        float4 v = make_float4(acc[r][0], acc[r][1], acc[r][2], acc[r][3]);
        *reinterpret_cast<float4*>(
            Z + (size_t)(row0 + ty * 4 + r) * 4096 + col0 + tx * 4) = v;
    }
}

// Cell phase (R4-validated math; z = sum of 2 K-partials). Flat 1:1 mapping:
// gid0 in [0,65536), 2 elements per thread.
__device__ __forceinline__ void cell_step(
    int gid0, const float* __restrict__ Z0, const float* __restrict__ Z1,
    float* __restrict__ h, float* __restrict__ c,
    const float* __restrict__ bias, float* __restrict__ y, int t)
{
#pragma unroll
    for (int it = 0; it < 2; it++) {
        int idx = gid0 + it * 65536;
        int b = idx >> 10, u = idx & 1023;
        size_t zo = (size_t)b * 4096;
        float zi = ldcg1(Z0 + zo + u)        + ldcg1(Z1 + zo + u)        + __ldg(&bias[u]);
        float zf = ldcg1(Z0 + zo + 1024 + u) + ldcg1(Z1 + zo + 1024 + u) + __ldg(&bias[1024 + u]);
        float zg = ldcg1(Z0 + zo + 2048 + u) + ldcg1(Z1 + zo + 2048 + u) + __ldg(&bias[2048 + u]);
        float zo4 = ldcg1(Z0 + zo + 3072 + u) + ldcg1(Z1 + zo + 3072 + u) + __ldg(&bias[3072 + u]);
        float si = 1.0f / (1.0f + expf(-zi));
        float sf = 1.0f / (1.0f + expf(-zf));
        float so = 1.0f / (1.0f + expf(-zo4));
        float cc = sf * c[idx] + si * tanhf(zg);
        c[idx] = cc;
        float hh = so * tanhf(cc);
        h[idx] = hh;
        if (y) y[((size_t)b * 256 + t) * 1024 + u] = hh;
    }
}

// Persistent kernel: full encoder scan + latent + decoder scan.
__global__ void __launch_bounds__(256, 2) vae_persistent(Params p)
{
    __shared__ __align__(16) float sA[4352];  // 2 x 32 x 68
    __shared__ __align__(16) float sB[4096];  // 2 x 32 x 64

    const int bid = blockIdx.x;
    const int tid = threadIdx.x;
    const int gid0 = bid * 256 + tid;   // 0..65535

    // zero all recurrent state
    for (int i = gid0; i < 786432; i += NBLK * 256) {
        g_h_enc[i] = 0.0f; g_h_dec[i] = 0.0f;
    }
    for (int i = gid0; i < 393216; i += NBLK * 256) {
        g_c_enc[i] = 0.0f; g_c_dec[i] = 0.0f;
    }
    grid_barrier();

    float* const z0 = g_z;
    float* const z1 = g_z + 524288;

    // ------------- encoder -------------
    for (int t = 0; t < 256; t++) {
        const int pw = t & 1, pr = pw ^ 1;
        gemm_step(sA, sB, bid, 1, 512, 1536, p.Wx[0], p.Wh[0],
                  nullptr, g_h_enc + pr * 131072, g_z, t, p.tokens, p.emb);
        grid_barrier();
        cell_step(gid0, z0, z1, g_h_enc + pw * 131072, g_c_enc, p.b[0], nullptr, t);
        grid_barrier();
        gemm_step(sA, sB, bid, 0, 1024, 2048, p.Wx[1], p.Wh[1],
                  g_h_enc + pw * 131072, g_h_enc + (2 + pr) * 131072,
                  g_z, t, p.tokens, p.emb);
        grid_barrier();
        cell_step(gid0, z0, z1, g_h_enc + (2 + pw) * 131072, g_c_enc + 131072,
                  p.b[1], nullptr, t);
        grid_barrier();
        gemm_step(sA, sB, bid, 0, 1024, 2048, p.Wx[2], p.Wh[2],
                  g_h_enc + (2 + pw) * 131072, g_h_enc + (4 + pr) * 131072,
                  g_z, t, p.tokens, p.emb);
        grid_barrier();
        cell_step(gid0, z0, z1, g_h_enc + (4 + pw) * 131072, g_c_enc + 262144,
                  p.b[2], nullptr, t);
        grid_barrier();
    }

    // ------------- latent: projects CELL state c3; eps ADDED (faithful) -----
    if (bid < 128) {
        const int row = bid;
        const float* c3 = g_c_enc + 262144 + row * 1024;
        for (int i = tid; i < 1024; i += 256) sA[i] = ldcg1(c3 + i);
        __syncthreads();
        const int col = tid;               // 256 threads = 256 latent cols
        float am = 0.0f, as = 0.0f;
        for (int k = 0; k < 1024; k++) {
            float a = sA[k];
            am = fmaf(a, __ldg(&p.w_mean[k * 256 + col]), am);
            as = fmaf(a, __ldg(&p.w_sigma[k * 256 + col]), as);
        }
        float mean = am + __ldg(&p.b_mean[col]);
        float sg   = as + __ldg(&p.b_sigma[col]);
        g_lat[row * 256 + col] = mean + expf(0.5f * sg)
                               + __ldg(&p.eps[row * 256 + col]);
        __syncthreads();
    }
    grid_barrier();

    // ------------- decoder -------------
    for (int t = 0; t < 256; t++) {
        const int pw = t & 1, pr = pw ^ 1;
        gemm_step(sA, sB, bid, 2, 768, 1792, p.Wx[3], p.Wh[3],
                  nullptr, g_h_dec + pr * 131072, g_z, t, p.tokens, p.emb);
        grid_barrier();
        cell_step(gid0, z0, z1, g_h_dec + pw * 131072, g_c_dec, p.b[3], nullptr, t);
        grid_barrier();
        gemm_step(sA, sB, bid, 0, 1024, 2048, p.Wx[4], p.Wh[4],
                  g_h_dec + pw * 131072, g_h_dec + (2 + pr) * 131072,
                  g_z, t, p.tokens, p.emb);
        grid_barrier();
        cell_step(gid0, z0, z1, g_h_dec + (2 + pw) * 131072, g_c_dec + 131072,
                  p.b[4], nullptr, t);
        grid_barrier();
        gemm_step(sA, sB, bid, 0, 1024, 2048, p.Wx[5], p.Wh[5],
                  g_h_dec + (2 + pw) * 131072, g_h_dec + (4 + pr) * 131072,
                  g_z, t, p.tokens, p.emb);
        grid_barrier();
        cell_step(gid0, z0, z1, g_h_dec + (4 + pw) * 131072, g_c_dec + 262144,
                  p.b[5], g_y, t);
        grid_barrier();
    }
}

// Dense logits GEMM (R4-validated): Z[32768,512] = Y[32768,1024] @ W + b.
__global__ void __launch_bounds__(128) logits_gemm(
    const float* __restrict__ A, const float* __restrict__ W,
    const float* __restrict__ bias, float* __restrict__ Z)
{
    __shared__ __align__(16) float As[16][68];
    __shared__ __align__(16) float Bs[16][64];
    const int tid = threadIdx.x;
    const int tx = tid & 15, ty = tid >> 4;
    const int row0 = blockIdx.y * 64, col0 = blockIdx.x * 64;

    float4 pa[2], pb[2];
#pragma unroll
    for (int j = 0; j < 2; j++) {
        int c = tid + j * 128;
        pa[j] = ldf4(A + (size_t)(row0 + (c >> 2)) * 1024 + (c & 3) * 4);
        int kk = c >> 4, nq = c & 15;
        pb[j] = ldf4(W + (size_t)kk * 512 + col0 + nq * 4);
    }
#pragma unroll
    for (int j = 0; j < 2; j++) {
        int c = tid + j * 128;
        int m = c >> 2, kb = (c & 3) * 4;
        As[kb + 0][m] = pa[j].x; As[kb + 1][m] = pa[j].y;
        As[kb + 2][m] = pa[j].z; As[kb + 3][m] = pa[j].w;
        int kk = c >> 4, nq = c & 15;
        *reinterpret_cast<float4*>(&Bs[kk][nq * 4]) = pb[j];
    }
    __syncthreads();

    float acc[8][4];
#pragma unroll
    for (int r = 0; r < 8; r++)
#pragma unroll
        for (int c2 = 0; c2 < 4; c2++) acc[r][c2] = 0.0f;

    for (int k0 = 16;; k0 += 16) {
        const bool more = (k0 < 1024);
        if (more) {
#pragma unroll
            for (int j = 0; j < 2; j++) {
                int c = tid + j * 128;
                pa[j] = ldf4(A + (size_t)(row0 + (c >> 2)) * 1024 + k0 + (c & 3) * 4);
                int kk = c >> 4, nq = c & 15;
                pb[j] = ldf4(W + (size_t)(k0 + kk) * 512 + col0 + nq * 4);
            }
        }
#pragma unroll
        for (int kk = 0; kk < 16; kk++) {
            float4 a0 = ldf4(&As[kk][ty * 8]);
            float4 a1 = ldf4(&As[kk][ty * 8 + 4]);
            float4 b  = ldf4(&Bs[kk][tx * 4]);
            float av[8] = {a0.x, a0.y, a0.z, a0.w, a1.x, a1.y, a1.z, a1.w};
            float bv[4] = {b.x, b.y, b.z, b.w};
#pragma unroll
            for (int r = 0; r < 8; r++)
#pragma unroll
                for (int c2 = 0; c2 < 4; c2++)
                    acc[r][c2] = fmaf(av[r], bv[c2], acc[r][c2]);
        }
        if (!more) break;
        __syncthreads();
#pragma unroll
        for (int j = 0; j < 2; j++) {
            int c = tid + j * 128;
            int m = c >> 2, kb = (c & 3) * 4;
            As[kb + 0][m] = pa[j].x; As[kb + 1][m] = pa[j].y;
            As[kb + 2][m] = pa[j].z; As[kb + 3][m] = pa[j].w;
            int kk = c >> 4, nq = c & 15;
            *reinterpret_cast<float4*>(&Bs[kk][nq * 4]) = pb[j];
        }
        __syncthreads();
    }

    float4 bv4 = ldf4(bias + col0 + tx * 4);
#pragma unroll
    for (int r = 0; r < 8; r++) {
        float4 v = make_float4(acc[r][0] + bv4.x, acc[r][1] + bv4.y,
                               acc[r][2] + bv4.z, acc[r][3] + bv4.w);
        *reinterpret_cast<float4*>(
            Z + (size_t)(row0 + ty * 8 + r) * 512 + col0 + tx * 4) = v;
    }
}

// argmax (first-occurrence tie-break, like jnp.argmax) + logits emission.
__global__ void emit_kernel(const float* __restrict__ logits,
                            float* __restrict__ out, long long out_size)
{
    int row = blockIdx.x;
    int tid = threadIdx.x;
    const float* lr = logits + (size_t)row * 512;

    float best = -3.402823466e38f; int bi = 0;
#pragma unroll
    for (int j = 0; j < 4; j++) {
        int vi = tid + j * 128;
        float v = lr[vi];
        if (v > best) { best = v; bi = vi; }
    }
    __shared__ float sv[128]; __shared__ int si[128];
    sv[tid] = best; si[tid] = bi;
    __syncthreads();
    for (int s = 64; s > 0; s >>= 1) {
        if (tid < s) {
            float v2 = sv[tid + s]; int i2 = si[tid + s];
            if (v2 > sv[tid] || (v2 == sv[tid] && i2 < si[tid])) {
                sv[tid] = v2; si[tid] = i2;
            }
        }
        __syncthreads();
    }
    int amax = si[0];

    if (out_size == BT_LL + BTV_LL) {
        if (tid == 0) out[row] = (float)amax;
        float* lo = out + BT_LL + (size_t)row * 512;
#pragma unroll
        for (int j = 0; j < 4; j++) lo[tid + j * 128] = lr[tid + j * 128];
    } else if (out_size == BTV_LL) {
        float* lo = out + (size_t)row * 512;
#pragma unroll
        for (int j = 0; j < 4; j++) lo[tid + j * 128] = lr[tid + j * 128];
    } else if (out_size == BT_LL) {
        if (tid == 0) reinterpret_cast<int*>(out)[row] = amax;
    } else {
        if (tid == 0 && (long long)row < out_size) out[row] = (float)amax;
#pragma unroll
        for (int j = 0; j < 4; j++) {
            long long o = BT_LL + (long long)row * 512 + tid + j * 128;
            if (o < out_size) out[o] = lr[tid + j * 128];
        }
    }
}

extern "C" void kernel_launch(void* const* d_in, const int* in_sizes, int n_in,
                              void* d_out, int out_size)
{
    Params p;
    p.tokens = (const int*)d_in[0];
    p.emb    = (const float*)d_in[1];
    p.Wx[0] = (const float*)d_in[2];  p.Wh[0] = (const float*)d_in[3];  p.b[0] = (const float*)d_in[4];
    p.Wx[1] = (const float*)d_in[5];  p.Wh[1] = (const float*)d_in[6];  p.b[1] = (const float*)d_in[7];
    p.Wx[2] = (const float*)d_in[8];  p.Wh[2] = (const float*)d_in[9];  p.b[2] = (const float*)d_in[10];
    p.Wx[3] = (const float*)d_in[11]; p.Wh[3] = (const float*)d_in[12]; p.b[3] = (const float*)d_in[13];
    p.Wx[4] = (const float*)d_in[14]; p.Wh[4] = (const float*)d_in[15]; p.b[4] = (const float*)d_in[16];
    p.Wx[5] = (const float*)d_in[17]; p.Wh[5] = (const float*)d_in[18]; p.b[5] = (const float*)d_in[19];
    p.w_mean  = (const float*)d_in[20];
    p.b_mean  = (const float*)d_in[21];
    p.w_sigma = (const float*)d_in[22];
    p.b_sigma = (const float*)d_in[23];
    const float* dec_w = (const float*)d_in[24];
    const float* dec_b = (const float*)d_in[25];
    p.eps = (const float*)d_in[26];

    float *y, *lg;
    cudaGetSymbolAddress((void**)&y,  g_y);
    cudaGetSymbolAddress((void**)&lg, g_logits);

    vae_persistent<<<NBLK, 256>>>(p);
    logits_gemm<<<dim3(8, 512), 128>>>(y, dec_w, dec_b, lg);
    emit_kernel<<<32768, 128>>>(lg, (float*)d_out, (long long)out_size);
}

// round 6
// speedup vs baseline: 1.8128x; 1.1550x over previous
#include <cuda_runtime.h>
#include <math.h>

#define NBLK 256
#define BT_LL  32768LL          // B*T
#define BTV_LL 16777216LL       // B*T*V

// ---------------- scratch (static device globals; no allocation) -------------
__device__ float g_h_enc[786432];    // 3 layers x 2 parity x [128,1024]
__device__ float g_c_enc[393216];    // 3 layers x [128,1024]
__device__ float g_h_dec[786432];
__device__ float g_c_dec[393216];
__device__ float g_z[2097152];       // 4 K-partials x [128,4096]
__device__ float g_lat[32768];       // [128,256]
__device__ float g_y[33554432];      // [128,256,1024] decoder top-layer h
__device__ float g_logits[16777216]; // [128,256,512]
__device__ unsigned g_bar_count;     // zero-initialized at module load
__device__ unsigned g_bar_phase;

struct Params {
    const int* tokens; const float* emb;
    const float* Wx[6]; const float* Wh[6]; const float* b[6]; // 0..2 enc, 3..5 dec
    const float* w_mean; const float* b_mean;
    const float* w_sigma; const float* b_sigma;
    const float* eps;
};

__device__ __forceinline__ float4 ldf4(const float* p) {
    return *reinterpret_cast<const float4*>(p);
}
__device__ __forceinline__ float4 ldcg4(const float* p) {
    float4 v;
    asm volatile("ld.global.cg.v4.f32 {%0,%1,%2,%3},[%4];"
                 : "=f"(v.x), "=f"(v.y), "=f"(v.z), "=f"(v.w)
                 : "l"(p) : "memory");
    return v;
}
__device__ __forceinline__ float ldcg1(const float* p) {
    float v;
    asm volatile("ld.global.cg.f32 %0,[%1];" : "=f"(v) : "l"(p) : "memory");
    return v;
}
__device__ __forceinline__ unsigned atom_add_acqrel(unsigned* p, unsigned v) {
    unsigned old;
    asm volatile("atom.add.acq_rel.gpu.global.u32 %0,[%1],%2;"
                 : "=r"(old) : "l"(p), "r"(v) : "memory");
    return old;
}
__device__ __forceinline__ void atom_add_release(unsigned* p, unsigned v) {
    unsigned old;
    asm volatile("atom.add.release.gpu.global.u32 %0,[%1],%2;"
                 : "=r"(old) : "l"(p), "r"(v) : "memory");
}
__device__ __forceinline__ unsigned ld_acquire(const unsigned* p) {
    unsigned v;
    asm volatile("ld.acquire.gpu.global.u32 %0,[%1];"
                 : "=r"(v) : "l"(p) : "memory");
    return v;
}
__device__ __forceinline__ void st_relaxed(unsigned* p, unsigned v) {
    asm volatile("st.relaxed.gpu.global.u32 [%0],%1;"
                 :: "l"(p), "r"(v) : "memory");
}

// Grid barrier (validated R4/R5). 256 blocks co-resident by construction:
// launch_bounds(256,2) -> regs<=128; smem 24.6KB/block -> >=2 blocks/SM.
__device__ __forceinline__ void grid_barrier() {
    __syncthreads();
    if (threadIdx.x == 0) {
        unsigned gen = ld_acquire(&g_bar_phase);
        unsigned old = atom_add_acqrel(&g_bar_count, 1u);
        if (old == NBLK - 1u) {
            st_relaxed(&g_bar_count, 0u);
            atom_add_release(&g_bar_phase, 1u);
        } else {
            while (ld_acquire(&g_bar_phase) == gen) {}
        }
    }
    __syncthreads();
}

// A-operand fetch (validated): 4 floats at logical col gk of A=[A1|A2].
//   mode 0: A1 dense [128,1024];  mode 1: A1 = emb[tokens[gm,t],:] (K1=512)
//   mode 2: A1 = [g_lat[gm,:] | emb-gather] (K1=768).  A2 = prev-parity h.
__device__ __forceinline__ float4 fetchA(
    int mode, int K1, const float* A1, const float* A2,
    const int* __restrict__ tokens, int t, const float* __restrict__ emb,
    int gm, int gk)
{
    if (gk >= K1) return ldcg4(A2 + gm * 1024 + (gk - K1));
    if (mode == 0) return ldcg4(A1 + gm * 1024 + gk);
    if (mode == 1) {
        int tok = __ldg(&tokens[gm * 256 + t]);
        return ldf4(emb + (size_t)tok * 512 + gk);
    }
    if (gk < 256) return ldcg4(g_lat + gm * 256 + gk);
    int tok = __ldg(&tokens[gm * 256 + t]);
    return ldf4(emb + (size_t)tok * 512 + (gk - 256));
}

// Split-K x4 GEMM phase: block bid -> K-quarter part=bid>>6, col tile tb=bid&63.
// Block tile BM=128 x BN=64 over K/4; per thread 8x4 outputs (1.5 smem-B/FMA).
// BK=16, double-buffered smem, one __syncthreads per k-tile.
__device__ void gemm_step(
    float* sA, float* sB, int bid, int mode, int K1, int KT,
    const float* __restrict__ Wx, const float* __restrict__ Wh,
    const float* A1, const float* A2, float* __restrict__ Z,
    int t, const int* __restrict__ tokens, const float* __restrict__ emb)
{
    const int tid = threadIdx.x;
    const int part = bid >> 6;
    const int col0 = (bid & 63) * 64;
    const int kq4 = KT >> 2;              // 384 / 512 / 448 (all /16)
    const int kbase = part * kq4;
    Z += part * 524288;

    const int tx = tid & 15, ty = tid >> 4;   // cols col0+tx*4, rows ty*8..+8
    const int mA0 = tid >> 2;                 // A chunk0 row (0..63)
    const int kqA = (tid & 3) * 4;            // A chunk k-quad
    const int kkB = tid >> 4, nqB = tid & 15; // B chunk

    float4 a0, a1, b0;

    // prefetch k-tile 0
    a0 = fetchA(mode, K1, A1, A2, tokens, t, emb, mA0,      kbase + kqA);
    a1 = fetchA(mode, K1, A1, A2, tokens, t, emb, mA0 + 64, kbase + kqA);
    {
        int gk = kbase + kkB;
        b0 = ldf4(((gk < K1) ? Wx + (size_t)gk * 4096
                             : Wh + (size_t)(gk - K1) * 4096) + col0 + nqB * 4);
    }
    {
        float* pa = sA;
        pa[(kqA + 0) * 132 + mA0] = a0.x; pa[(kqA + 1) * 132 + mA0] = a0.y;
        pa[(kqA + 2) * 132 + mA0] = a0.z; pa[(kqA + 3) * 132 + mA0] = a0.w;
        pa[(kqA + 0) * 132 + mA0 + 64] = a1.x; pa[(kqA + 1) * 132 + mA0 + 64] = a1.y;
        pa[(kqA + 2) * 132 + mA0 + 64] = a1.z; pa[(kqA + 3) * 132 + mA0 + 64] = a1.w;
        *reinterpret_cast<float4*>(sB + kkB * 64 + nqB * 4) = b0;
    }
    __syncthreads();

    float acc[8][4];
#pragma unroll
    for (int r = 0; r < 8; r++)
#pragma unroll
        for (int c2 = 0; c2 < 4; c2++) acc[r][c2] = 0.0f;

    const int nt = kq4 >> 4;
    for (int it = 0; it < nt; it++) {
        const int cur = it & 1;
        const bool more = (it + 1 < nt);
        if (more) {
            const int k0 = kbase + (it + 1) * 16;
            a0 = fetchA(mode, K1, A1, A2, tokens, t, emb, mA0,      k0 + kqA);
            a1 = fetchA(mode, K1, A1, A2, tokens, t, emb, mA0 + 64, k0 + kqA);
            int gk = k0 + kkB;
            b0 = ldf4(((gk < K1) ? Wx + (size_t)gk * 4096
                                 : Wh + (size_t)(gk - K1) * 4096) + col0 + nqB * 4);
        }
        const float* pa = sA + cur * 2112;
        const float* pb = sB + cur * 1024;
#pragma unroll
        for (int kk = 0; kk < 16; kk++) {
            float4 av0 = ldf4(pa + kk * 132 + ty * 8);
            float4 av1 = ldf4(pa + kk * 132 + ty * 8 + 4);
            float4 bv4 = ldf4(pb + kk * 64 + tx * 4);
            float av[8] = {av0.x, av0.y, av0.z, av0.w, av1.x, av1.y, av1.z, av1.w};
            float bv[4] = {bv4.x, bv4.y, bv4.z, bv4.w};
#pragma unroll
            for (int r = 0; r < 8; r++)
#pragma unroll
                for (int c2 = 0; c2 < 4; c2++)
                    acc[r][c2] = fmaf(av[r], bv[c2], acc[r][c2]);
        }
        if (more) {
            float* pa2 = sA + (cur ^ 1) * 2112;
            pa2[(kqA + 0) * 132 + mA0] = a0.x; pa2[(kqA + 1) * 132 + mA0] = a0.y;
            pa2[(kqA + 2) * 132 + mA0] = a0.z; pa2[(kqA + 3) * 132 + mA0] = a0.w;
            pa2[(kqA + 0) * 132 + mA0 + 64] = a1.x; pa2[(kqA + 1) * 132 + mA0 + 64] = a1.y;
            pa2[(kqA + 2) * 132 + mA0 + 64] = a1.z; pa2[(kqA + 3) * 132 + mA0 + 64] = a1.w;
            *reinterpret_cast<float4*>(sB + (cur ^ 1) * 1024 + kkB * 64 + nqB * 4) = b0;
        }
        __syncthreads();
    }

#pragma unroll
    for (int r = 0; r < 8; r++) {
        float4 v = make_float4(acc[r][0], acc[r][1], acc[r][2], acc[r][3]);
        *reinterpret_cast<float4*>(
            Z + (size_t)(ty * 8 + r) * 4096 + col0 + tx * 4) = v;
    }
}

// Cell phase (validated math; z = sum of 4 K-partials). Flat 1:1 mapping.
__device__ __forceinline__ void cell_step(
    int gid0, float* __restrict__ h, float* __restrict__ c,
    const float* __restrict__ bias, float* __restrict__ y, int t)
{
#pragma unroll
    for (int it = 0; it < 2; it++) {
        int idx = gid0 + it * 65536;
        int b = idx >> 10, u = idx & 1023;
        size_t zo = (size_t)b * 4096;
        float zi = __ldg(&bias[u]),        zf = __ldg(&bias[1024 + u]);
        float zg = __ldg(&bias[2048 + u]), zon = __ldg(&bias[3072 + u]);
#pragma unroll
        for (int pp = 0; pp < 4; pp++) {
            const float* Zp = g_z + pp * 524288 + zo;
            zi += ldcg1(Zp + u);
            zf += ldcg1(Zp + 1024 + u);
            zg += ldcg1(Zp + 2048 + u);
            zon += ldcg1(Zp + 3072 + u);
        }
        float si = 1.0f / (1.0f + expf(-zi));
        float sf = 1.0f / (1.0f + expf(-zf));
        float so = 1.0f / (1.0f + expf(-zon));
        float cc = sf * c[idx] + si * tanhf(zg);
        c[idx] = cc;
        float hh = so * tanhf(cc);
        h[idx] = hh;
        if (y) y[((size_t)b * 256 + t) * 1024 + u] = hh;
    }
}

// Persistent kernel: full encoder scan + latent + decoder scan.
__global__ void __launch_bounds__(256, 2) vae_persistent(Params p)
{
    __shared__ __align__(16) float sA[4224];  // 2 x 16 x 132
    __shared__ __align__(16) float sB[2048];  // 2 x 16 x 64

    const int bid = blockIdx.x;
    const int tid = threadIdx.x;
    const int gid0 = bid * 256 + tid;   // 0..65535

    // zero all recurrent state
    for (int i = gid0; i < 786432; i += NBLK * 256) {
        g_h_enc[i] = 0.0f; g_h_dec[i] = 0.0f;
    }
    for (int i = gid0; i < 393216; i += NBLK * 256) {
        g_c_enc[i] = 0.0f; g_c_dec[i] = 0.0f;
    }
    grid_barrier();

    // ------------- encoder -------------
    for (int t = 0; t < 256; t++) {
        const int pw = t & 1, pr = pw ^ 1;
        gemm_step(sA, sB, bid, 1, 512, 1536, p.Wx[0], p.Wh[0],
                  nullptr, g_h_enc + pr * 131072, g_z, t, p.tokens, p.emb);
        grid_barrier();
        cell_step(gid0, g_h_enc + pw * 131072, g_c_enc, p.b[0], nullptr, t);
        grid_barrier();
        gemm_step(sA, sB, bid, 0, 1024, 2048, p.Wx[1], p.Wh[1],
                  g_h_enc + pw * 131072, g_h_enc + (2 + pr) * 131072,
                  g_z, t, p.tokens, p.emb);
        grid_barrier();
        cell_step(gid0, g_h_enc + (2 + pw) * 131072, g_c_enc + 131072,
                  p.b[1], nullptr, t);
        grid_barrier();
        gemm_step(sA, sB, bid, 0, 1024, 2048, p.Wx[2], p.Wh[2],
                  g_h_enc + (2 + pw) * 131072, g_h_enc + (4 + pr) * 131072,
                  g_z, t, p.tokens, p.emb);
        grid_barrier();
        cell_step(gid0, g_h_enc + (4 + pw) * 131072, g_c_enc + 262144,
                  p.b[2], nullptr, t);
        grid_barrier();
    }

    // ------------- latent: projects CELL state c3; eps ADDED (faithful) -----
    if (bid < 128) {
        const int row = bid;
        const float* c3 = g_c_enc + 262144 + row * 1024;
        for (int i = tid; i < 1024; i += 256) sA[i] = ldcg1(c3 + i);
        __syncthreads();
        const int col = tid;               // 256 threads = 256 latent cols
        float am = 0.0f, as = 0.0f;
        for (int k = 0; k < 1024; k++) {
            float a = sA[k];
            am = fmaf(a, __ldg(&p.w_mean[k * 256 + col]), am);
            as = fmaf(a, __ldg(&p.w_sigma[k * 256 + col]), as);
        }
        float mean = am + __ldg(&p.b_mean[col]);
        float sg   = as + __ldg(&p.b_sigma[col]);
        g_lat[row * 256 + col] = mean + expf(0.5f * sg)
                               + __ldg(&p.eps[row * 256 + col]);
        __syncthreads();
    }
    grid_barrier();

    // ------------- decoder -------------
    for (int t = 0; t < 256; t++) {
        const int pw = t & 1, pr = pw ^ 1;
        gemm_step(sA, sB, bid, 2, 768, 1792, p.Wx[3], p.Wh[3],
                  nullptr, g_h_dec + pr * 131072, g_z, t, p.tokens, p.emb);
        grid_barrier();
        cell_step(gid0, g_h_dec + pw * 131072, g_c_dec, p.b[3], nullptr, t);
        grid_barrier();
        gemm_step(sA, sB, bid, 0, 1024, 2048, p.Wx[4], p.Wh[4],
                  g_h_dec + pw * 131072, g_h_dec + (2 + pr) * 131072,
                  g_z, t, p.tokens, p.emb);
        grid_barrier();
        cell_step(gid0, g_h_dec + (2 + pw) * 131072, g_c_dec + 131072,
                  p.b[4], nullptr, t);
        grid_barrier();
        gemm_step(sA, sB, bid, 0, 1024, 2048, p.Wx[5], p.Wh[5],
                  g_h_dec + (2 + pw) * 131072, g_h_dec + (4 + pr) * 131072,
                  g_z, t, p.tokens, p.emb);
        grid_barrier();
        cell_step(gid0, g_h_dec + (4 + pw) * 131072, g_c_dec + 262144,
                  p.b[5], g_y, t);
        grid_barrier();
    }
}

// Dense logits GEMM (validated): Z[32768,512] = Y[32768,1024] @ W + b.
__global__ void __launch_bounds__(128) logits_gemm(
    const float* __restrict__ A, const float* __restrict__ W,
    const float* __restrict__ bias, float* __restrict__ Z)
{
    __shared__ __align__(16) float As[16][68];
    __shared__ __align__(16) float Bs[16][64];
    const int tid = threadIdx.x;
    const int tx = tid & 15, ty = tid >> 4;
    const int row0 = blockIdx.y * 64, col0 = blockIdx.x * 64;

    float4 pa[2], pb[2];
#pragma unroll
    for (int j = 0; j < 2; j++) {
        int c = tid + j * 128;
        pa[j] = ldf4(A + (size_t)(row0 + (c >> 2)) * 1024 + (c & 3) * 4);
        int kk = c >> 4, nq = c & 15;
        pb[j] = ldf4(W + (size_t)kk * 512 + col0 + nq * 4);
    }
#pragma unroll
    for (int j = 0; j < 2; j++) {
        int c = tid + j * 128;
        int m = c >> 2, kb = (c & 3) * 4;
        As[kb + 0][m] = pa[j].x; As[kb + 1][m] = pa[j].y;
        As[kb + 2][m] = pa[j].z; As[kb + 3][m] = pa[j].w;
        int kk = c >> 4, nq = c & 15;
        *reinterpret_cast<float4*>(&Bs[kk][nq * 4]) = pb[j];
    }
    __syncthreads();

    float acc[8][4];
#pragma unroll
    for (int r = 0; r < 8; r++)
#pragma unroll
        for (int c2 = 0; c2 < 4; c2++) acc[r][c2] = 0.0f;

    for (int k0 = 16;; k0 += 16) {
        const bool more = (k0 < 1024);
        if (more) {
#pragma unroll
            for (int j = 0; j < 2; j++) {
                int c = tid + j * 128;
                pa[j] = ldf4(A + (size_t)(row0 + (c >> 2)) * 1024 + k0 + (c & 3) * 4);
                int kk = c >> 4, nq = c & 15;
                pb[j] = ldf4(W + (size_t)(k0 + kk) * 512 + col0 + nq * 4);
            }
        }
#pragma unroll
        for (int kk = 0; kk < 16; kk++) {
            float4 a0 = ldf4(&As[kk][ty * 8]);
            float4 a1 = ldf4(&As[kk][ty * 8 + 4]);
            float4 b  = ldf4(&Bs[kk][tx * 4]);
            float av[8] = {a0.x, a0.y, a0.z, a0.w, a1.x, a1.y, a1.z, a1.w};
            float bv[4] = {b.x, b.y, b.z, b.w};
#pragma unroll
            for (int r = 0; r < 8; r++)
#pragma unroll
                for (int c2 = 0; c2 < 4; c2++)
                    acc[r][c2] = fmaf(av[r], bv[c2], acc[r][c2]);
        }
        if (!more) break;
        __syncthreads();
#pragma unroll
        for (int j = 0; j < 2; j++) {
            int c = tid + j * 128;
            int m = c >> 2, kb = (c & 3) * 4;
            As[kb + 0][m] = pa[j].x; As[kb + 1][m] = pa[j].y;
            As[kb + 2][m] = pa[j].z; As[kb + 3][m] = pa[j].w;
            int kk = c >> 4, nq = c & 15;
            *reinterpret_cast<float4*>(&Bs[kk][nq * 4]) = pb[j];
        }
        __syncthreads();
    }

    float4 bv4 = ldf4(bias + col0 + tx * 4);
#pragma unroll
    for (int r = 0; r < 8; r++) {
        float4 v = make_float4(acc[r][0] + bv4.x, acc[r][1] + bv4.y,
                               acc[r][2] + bv4.z, acc[r][3] + bv4.w);
        *reinterpret_cast<float4*>(
            Z + (size_t)(row0 + ty * 8 + r) * 512 + col0 + tx * 4) = v;
    }
}

// argmax (first-occurrence tie-break, like jnp.argmax) + logits emission.
__global__ void emit_kernel(const float* __restrict__ logits,
                            float* __restrict__ out, long long out_size)
{
    int row = blockIdx.x;
    int tid = threadIdx.x;
    const float* lr = logits + (size_t)row * 512;

    float best = -3.402823466e38f; int bi = 0;
#pragma unroll
    for (int j = 0; j < 4; j++) {
        int vi = tid + j * 128;
        float v = lr[vi];
        if (v > best) { best = v; bi = vi; }
    }
    __shared__ float sv[128]; __shared__ int si[128];
    sv[tid] = best; si[tid] = bi;
    __syncthreads();
    for (int s = 64; s > 0; s >>= 1) {
        if (tid < s) {
            float v2 = sv[tid + s]; int i2 = si[tid + s];
            if (v2 > sv[tid] || (v2 == sv[tid] && i2 < si[tid])) {
                sv[tid] = v2; si[tid] = i2;
            }
        }
        __syncthreads();
    }
    int amax = si[0];

    if (out_size == BT_LL + BTV_LL) {
        if (tid == 0) out[row] = (float)amax;
        float* lo = out + BT_LL + (size_t)row * 512;
#pragma unroll
        for (int j = 0; j < 4; j++) lo[tid + j * 128] = lr[tid + j * 128];
    } else if (out_size == BTV_LL) {
        float* lo = out + (size_t)row * 512;
#pragma unroll
        for (int j = 0; j < 4; j++) lo[tid + j * 128] = lr[tid + j * 128];
    } else if (out_size == BT_LL) {
        if (tid == 0) reinterpret_cast<int*>(out)[row] = amax;
    } else {
        if (tid == 0 && (long long)row < out_size) out[row] = (float)amax;
#pragma unroll
        for (int j = 0; j < 4; j++) {
            long long o = BT_LL + (long long)row * 512 + tid + j * 128;
            if (o < out_size) out[o] = lr[tid + j * 128];
        }
    }
}

extern "C" void kernel_launch(void* const* d_in, const int* in_sizes, int n_in,
                              void* d_out, int out_size)
{
    Params p;
    p.tokens = (const int*)d_in[0];
    p.emb    = (const float*)d_in[1];
    p.Wx[0] = (const float*)d_in[2];  p.Wh[0] = (const float*)d_in[3];  p.b[0] = (const float*)d_in[4];
    p.Wx[1] = (const float*)d_in[5];  p.Wh[1] = (const float*)d_in[6];  p.b[1] = (const float*)d_in[7];
    p.Wx[2] = (const float*)d_in[8];  p.Wh[2] = (const float*)d_in[9];  p.b[2] = (const float*)d_in[10];
    p.Wx[3] = (const float*)d_in[11]; p.Wh[3] = (const float*)d_in[12]; p.b[3] = (const float*)d_in[13];
    p.Wx[4] = (const float*)d_in[14]; p.Wh[4] = (const float*)d_in[15]; p.b[4] = (const float*)d_in[16];
    p.Wx[5] = (const float*)d_in[17]; p.Wh[5] = (const float*)d_in[18]; p.b[5] = (const float*)d_in[19];
    p.w_mean  = (const float*)d_in[20];
    p.b_mean  = (const float*)d_in[21];
    p.w_sigma = (const float*)d_in[22];
    p.b_sigma = (const float*)d_in[23];
    const float* dec_w = (const float*)d_in[24];
    const float* dec_b = (const float*)d_in[25];
    p.eps = (const float*)d_in[26];

    float *y, *lg;
    cudaGetSymbolAddress((void**)&y,  g_y);
    cudaGetSymbolAddress((void**)&lg, g_logits);

    vae_persistent<<<NBLK, 256>>>(p);
    logits_gemm<<<dim3(8, 512), 128>>>(y, dec_w, dec_b, lg);
    emit_kernel<<<32768, 128>>>(lg, (float*)d_out, (long long)out_size);
}

// round 7
// speedup vs baseline: 1.8993x; 1.0477x over previous
#include <cuda_runtime.h>
#include <math.h>

#define NBLK 256
#define BT_LL  32768LL          // B*T
#define BTV_LL 16777216LL       // B*T*V

// ---------------- scratch (static device globals; no allocation) -------------
__device__ float g_h_enc[786432];    // 3 layers x 2 parity x [128,1024]
__device__ float g_c_enc[393216];    // 3 layers x [128,1024]
__device__ float g_h_dec[786432];
__device__ float g_c_dec[393216];
__device__ float g_z[6291456];       // 3 layers x 4 K-partials x [128,4096]
__device__ float g_lat[32768];       // [128,256]
__device__ float g_y[33554432];      // [128,256,1024] decoder top-layer h
__device__ float g_logits[16777216]; // [128,256,512]
__device__ unsigned g_bar_count;     // zero-initialized at module load
__device__ unsigned g_bar_phase;

struct Params {
    const int* tokens; const float* emb;
    const float* Wx[6]; const float* Wh[6]; const float* b[6]; // 0..2 enc, 3..5 dec
    const float* w_mean; const float* b_mean;
    const float* w_sigma; const float* b_sigma;
    const float* eps;
};

__device__ __forceinline__ float4 ldf4(const float* p) {
    return *reinterpret_cast<const float4*>(p);
}
__device__ __forceinline__ float4 ldcg4(const float* p) {
    float4 v;
    asm volatile("ld.global.cg.v4.f32 {%0,%1,%2,%3},[%4];"
                 : "=f"(v.x), "=f"(v.y), "=f"(v.z), "=f"(v.w)
                 : "l"(p) : "memory");
    return v;
}
__device__ __forceinline__ float ldcg1(const float* p) {
    float v;
    asm volatile("ld.global.cg.f32 %0,[%1];" : "=f"(v) : "l"(p) : "memory");
    return v;
}
__device__ __forceinline__ unsigned atom_add_acqrel(unsigned* p, unsigned v) {
    unsigned old;
    asm volatile("atom.add.acq_rel.gpu.global.u32 %0,[%1],%2;"
                 : "=r"(old) : "l"(p), "r"(v) : "memory");
    return old;
}
__device__ __forceinline__ void atom_add_release(unsigned* p, unsigned v) {
    unsigned old;
    asm volatile("atom.add.release.gpu.global.u32 %0,[%1],%2;"
                 : "=r"(old) : "l"(p), "r"(v) : "memory");
}
__device__ __forceinline__ unsigned ld_acquire(const unsigned* p) {
    unsigned v;
    asm volatile("ld.acquire.gpu.global.u32 %0,[%1];"
                 : "=r"(v) : "l"(p) : "memory");
    return v;
}
__device__ __forceinline__ void st_relaxed(unsigned* p, unsigned v) {
    asm volatile("st.relaxed.gpu.global.u32 [%0],%1;"
                 :: "l"(p), "r"(v) : "memory");
}

// Grid barrier (validated R4-R6). 256 blocks co-resident by construction:
// launch_bounds(256,2) -> regs<=128; smem 24.6KB/block -> >=2 blocks/SM.
__device__ __forceinline__ void grid_barrier() {
    __syncthreads();
    if (threadIdx.x == 0) {
        unsigned gen = ld_acquire(&g_bar_phase);
        unsigned old = atom_add_acqrel(&g_bar_count, 1u);
        if (old == NBLK - 1u) {
            st_relaxed(&g_bar_count, 0u);
            atom_add_release(&g_bar_phase, 1u);
        } else {
            while (ld_acquire(&g_bar_phase) == gen) {}
        }
    }
    __syncthreads();
}

// A-operand fetch (validated): 4 floats at logical col gk of A=[A1|A2].
//   mode 0: A1 dense [128,1024];  mode 1: A1 = emb[tokens[gm,t],:] (K1=512)
//   mode 2: A1 = [g_lat[gm,:] | emb-gather] (K1=768).  A2 = prev-parity h.
__device__ __forceinline__ float4 fetchA(
    int mode, int K1, const float* A1, const float* A2,
    const int* __restrict__ tokens, int t, const float* __restrict__ emb,
    int gm, int gk)
{
    if (gk >= K1) return ldcg4(A2 + gm * 1024 + (gk - K1));
    if (mode == 0) return ldcg4(A1 + gm * 1024 + gk);
    if (mode == 1) {
        int tok = __ldg(&tokens[gm * 256 + t]);
        return ldf4(emb + (size_t)tok * 512 + gk);
    }
    if (gk < 256) return ldcg4(g_lat + gm * 256 + gk);
    int tok = __ldg(&tokens[gm * 256 + t]);
    return ldf4(emb + (size_t)tok * 512 + (gk - 256));
}

// Split-K x4 GEMM phase (validated R6 core): block bid -> K-quarter
// part=bid>>6, col tile bid&63. Block tile BM=128 x BN=64 over K/4; per
// thread 8x4 outputs. BK=16, double-buffered smem, one sync per k-tile.
__device__ void gemm_step(
    float* sA, float* sB, int bid, int mode, int K1, int KT,
    const float* __restrict__ Wx, const float* __restrict__ Wh,
    const float* A1, const float* A2, float* __restrict__ Z,
    int t, const int* __restrict__ tokens, const float* __restrict__ emb)
{
    const int tid = threadIdx.x;
    const int part = bid >> 6;
    const int col0 = (bid & 63) * 64;
    const int kq4 = KT >> 2;              // 384 / 512 / 448 (all /16)
    const int kbase = part * kq4;
    Z += part * 524288;

    const int tx = tid & 15, ty = tid >> 4;   // cols col0+tx*4, rows ty*8..+8
    const int mA0 = tid >> 2;                 // A chunk0 row (0..63)
    const int kqA = (tid & 3) * 4;            // A chunk k-quad
    const int kkB = tid >> 4, nqB = tid & 15; // B chunk

    float4 a0, a1, b0;

    // prefetch k-tile 0
    a0 = fetchA(mode, K1, A1, A2, tokens, t, emb, mA0,      kbase + kqA);
    a1 = fetchA(mode, K1, A1, A2, tokens, t, emb, mA0 + 64, kbase + kqA);
    {
        int gk = kbase + kkB;
        b0 = ldf4(((gk < K1) ? Wx + (size_t)gk * 4096
                             : Wh + (size_t)(gk - K1) * 4096) + col0 + nqB * 4);
    }
    {
        float* pa = sA;
        pa[(kqA + 0) * 132 + mA0] = a0.x; pa[(kqA + 1) * 132 + mA0] = a0.y;
        pa[(kqA + 2) * 132 + mA0] = a0.z; pa[(kqA + 3) * 132 + mA0] = a0.w;
        pa[(kqA + 0) * 132 + mA0 + 64] = a1.x; pa[(kqA + 1) * 132 + mA0 + 64] = a1.y;
        pa[(kqA + 2) * 132 + mA0 + 64] = a1.z; pa[(kqA + 3) * 132 + mA0 + 64] = a1.w;
        *reinterpret_cast<float4*>(sB + kkB * 64 + nqB * 4) = b0;
    }
    __syncthreads();

    float acc[8][4];
#pragma unroll
    for (int r = 0; r < 8; r++)
#pragma unroll
        for (int c2 = 0; c2 < 4; c2++) acc[r][c2] = 0.0f;

    const int nt = kq4 >> 4;
    for (int it = 0; it < nt; it++) {
        const int cur = it & 1;
        const bool more = (it + 1 < nt);
        if (more) {
            const int k0 = kbase + (it + 1) * 16;
            a0 = fetchA(mode, K1, A1, A2, tokens, t, emb, mA0,      k0 + kqA);
            a1 = fetchA(mode, K1, A1, A2, tokens, t, emb, mA0 + 64, k0 + kqA);
            int gk = k0 + kkB;
            b0 = ldf4(((gk < K1) ? Wx + (size_t)gk * 4096
                                 : Wh + (size_t)(gk - K1) * 4096) + col0 + nqB * 4);
        }
        const float* pa = sA + cur * 2112;
        const float* pb = sB + cur * 1024;
#pragma unroll
        for (int kk = 0; kk < 16; kk++) {
            float4 av0 = ldf4(pa + kk * 132 + ty * 8);
            float4 av1 = ldf4(pa + kk * 132 + ty * 8 + 4);
            float4 bv4 = ldf4(pb + kk * 64 + tx * 4);
            float av[8] = {av0.x, av0.y, av0.z, av0.w, av1.x, av1.y, av1.z, av1.w};
            float bv[4] = {bv4.x, bv4.y, bv4.z, bv4.w};
#pragma unroll
            for (int r = 0; r < 8; r++)
#pragma unroll
                for (int c2 = 0; c2 < 4; c2++)
                    acc[r][c2] = fmaf(av[r], bv[c2], acc[r][c2]);
        }
        if (more) {
            float* pa2 = sA + (cur ^ 1) * 2112;
            pa2[(kqA + 0) * 132 + mA0] = a0.x; pa2[(kqA + 1) * 132 + mA0] = a0.y;
            pa2[(kqA + 2) * 132 + mA0] = a0.z; pa2[(kqA + 3) * 132 + mA0] = a0.w;
            pa2[(kqA + 0) * 132 + mA0 + 64] = a1.x; pa2[(kqA + 1) * 132 + mA0 + 64] = a1.y;
            pa2[(kqA + 2) * 132 + mA0 + 64] = a1.z; pa2[(kqA + 3) * 132 + mA0 + 64] = a1.w;
            *reinterpret_cast<float4*>(sB + (cur ^ 1) * 1024 + kkB * 64 + nqB * 4) = b0;
        }
        __syncthreads();
    }

#pragma unroll
    for (int r = 0; r < 8; r++) {
        float4 v = make_float4(acc[r][0], acc[r][1], acc[r][2], acc[r][3]);
        *reinterpret_cast<float4*>(
            Z + (size_t)(ty * 8 + r) * 4096 + col0 + tx * 4) = v;
    }
}

// Cell phase (validated math; z = sum of 4 K-partials at zbase). Flat mapping.
__device__ __forceinline__ void cell_step(
    int gid0, const float* __restrict__ zbase,
    float* __restrict__ h, float* __restrict__ c,
    const float* __restrict__ bias, float* __restrict__ y, int t)
{
#pragma unroll
    for (int it = 0; it < 2; it++) {
        int idx = gid0 + it * 65536;
        int b = idx >> 10, u = idx & 1023;
        size_t zo = (size_t)b * 4096;
        float zi = __ldg(&bias[u]),        zf = __ldg(&bias[1024 + u]);
        float zg = __ldg(&bias[2048 + u]), zon = __ldg(&bias[3072 + u]);
#pragma unroll
        for (int pp = 0; pp < 4; pp++) {
            const float* Zp = zbase + pp * 524288 + zo;
            zi += ldcg1(Zp + u);
            zf += ldcg1(Zp + 1024 + u);
            zg += ldcg1(Zp + 2048 + u);
            zon += ldcg1(Zp + 3072 + u);
        }
        float si = 1.0f / (1.0f + expf(-zi));
        float sf = 1.0f / (1.0f + expf(-zf));
        float so = 1.0f / (1.0f + expf(-zon));
        float cc = sf * c[idx] + si * tanhf(zg);
        c[idx] = cc;
        float hh = so * tanhf(cc);
        h[idx] = hh;
        if (y) y[((size_t)b * 256 + t) * 1024 + u] = hh;
    }
}

// Persistent kernel: wavefront-pipelined encoder scan + latent + decoder scan.
// Wavefront s computes GEMMs for (l0,t=s), (l1,s-1), (l2,s-2) concurrently
// (independent along the anti-diagonal), then one barrier, then all cells,
// then one barrier. h parity keys off wavefront: producer (cell at wavefront
// s) writes parity s&1; both consumers at wavefront s+1 read parity s&1.
__global__ void __launch_bounds__(256, 2) vae_persistent(Params p)
{
    __shared__ __align__(16) float sA[4224];  // 2 x 16 x 132
    __shared__ __align__(16) float sB[2048];  // 2 x 16 x 64

    const int bid = blockIdx.x;
    const int tid = threadIdx.x;
    const int gid0 = bid * 256 + tid;   // 0..65535

    // zero all recurrent state
    for (int i = gid0; i < 786432; i += NBLK * 256) {
        g_h_enc[i] = 0.0f; g_h_dec[i] = 0.0f;
    }
    for (int i = gid0; i < 393216; i += NBLK * 256) {
        g_c_enc[i] = 0.0f; g_c_dec[i] = 0.0f;
    }
    grid_barrier();

    // ------------- encoder (wavefronts s = 0..257) -------------
    for (int s = 0; s < 258; s++) {
        const int pw = s & 1, pr = pw ^ 1;
        // GEMM phase: up to 3 independent layer-GEMMs (uniform flow: s uniform)
        {
            int t0 = s;
            if (t0 < 256)
                gemm_step(sA, sB, bid, 1, 512, 1536, p.Wx[0], p.Wh[0],
                          nullptr, g_h_enc + pr * 131072,
                          g_z, t0, p.tokens, p.emb);
            int t1 = s - 1;
            if (t1 >= 0 && t1 < 256)
                gemm_step(sA, sB, bid, 0, 1024, 2048, p.Wx[1], p.Wh[1],
                          g_h_enc + pr * 131072, g_h_enc + (2 + pr) * 131072,
                          g_z + 2097152, t1, p.tokens, p.emb);
            int t2 = s - 2;
            if (t2 >= 0 && t2 < 256)
                gemm_step(sA, sB, bid, 0, 1024, 2048, p.Wx[2], p.Wh[2],
                          g_h_enc + (2 + pr) * 131072, g_h_enc + (4 + pr) * 131072,
                          g_z + 4194304, t2, p.tokens, p.emb);
        }
        grid_barrier();
        // Cell phase for all active layers
        {
            int t0 = s;
            if (t0 < 256)
                cell_step(gid0, g_z, g_h_enc + pw * 131072, g_c_enc,
                          p.b[0], nullptr, t0);
            int t1 = s - 1;
            if (t1 >= 0 && t1 < 256)
                cell_step(gid0, g_z + 2097152, g_h_enc + (2 + pw) * 131072,
                          g_c_enc + 131072, p.b[1], nullptr, t1);
            int t2 = s - 2;
            if (t2 >= 0 && t2 < 256)
                cell_step(gid0, g_z + 4194304, g_h_enc + (4 + pw) * 131072,
                          g_c_enc + 262144, p.b[2], nullptr, t2);
        }
        grid_barrier();
    }

    // ------------- latent: projects CELL state c3; eps ADDED (faithful) -----
    if (bid < 128) {
        const int row = bid;
        const float* c3 = g_c_enc + 262144 + row * 1024;
        for (int i = tid; i < 1024; i += 256) sA[i] = ldcg1(c3 + i);
        __syncthreads();
        const int col = tid;               // 256 threads = 256 latent cols
        float am = 0.0f, as = 0.0f;
        for (int k = 0; k < 1024; k++) {
            float a = sA[k];
            am = fmaf(a, __ldg(&p.w_mean[k * 256 + col]), am);
            as = fmaf(a, __ldg(&p.w_sigma[k * 256 + col]), as);
        }
        float mean = am + __ldg(&p.b_mean[col]);
        float sg   = as + __ldg(&p.b_sigma[col]);
        g_lat[row * 256 + col] = mean + expf(0.5f * sg)
                               + __ldg(&p.eps[row * 256 + col]);
        __syncthreads();
    }
    grid_barrier();

    // ------------- decoder (wavefronts s = 0..257) -------------
    for (int s = 0; s < 258; s++) {
        const int pw = s & 1, pr = pw ^ 1;
        {
            int t0 = s;
            if (t0 < 256)
                gemm_step(sA, sB, bid, 2, 768, 1792, p.Wx[3], p.Wh[3],
                          nullptr, g_h_dec + pr * 131072,
                          g_z, t0, p.tokens, p.emb);
            int t1 = s - 1;
            if (t1 >= 0 && t1 < 256)
                gemm_step(sA, sB, bid, 0, 1024, 2048, p.Wx[4], p.Wh[4],
                          g_h_dec + pr * 131072, g_h_dec + (2 + pr) * 131072,
                          g_z + 2097152, t1, p.tokens, p.emb);
            int t2 = s - 2;
            if (t2 >= 0 && t2 < 256)
                gemm_step(sA, sB, bid, 0, 1024, 2048, p.Wx[5], p.Wh[5],
                          g_h_dec + (2 + pr) * 131072, g_h_dec + (4 + pr) * 131072,
                          g_z + 4194304, t2, p.tokens, p.emb);
        }
        grid_barrier();
        {
            int t0 = s;
            if (t0 < 256)
                cell_step(gid0, g_z, g_h_dec + pw * 131072, g_c_dec,
                          p.b[3], nullptr, t0);
            int t1 = s - 1;
            if (t1 >= 0 && t1 < 256)
                cell_step(gid0, g_z + 2097152, g_h_dec + (2 + pw) * 131072,
                          g_c_dec + 131072, p.b[4], nullptr, t1);
            int t2 = s - 2;
            if (t2 >= 0 && t2 < 256)
                cell_step(gid0, g_z + 4194304, g_h_dec + (4 + pw) * 131072,
                          g_c_dec + 262144, p.b[5], g_y, t2);
        }
        grid_barrier();
    }
}

// Dense logits GEMM (validated): Z[32768,512] = Y[32768,1024] @ W + b.
__global__ void __launch_bounds__(128) logits_gemm(
    const float* __restrict__ A, const float* __restrict__ W,
    const float* __restrict__ bias, float* __restrict__ Z)
{
    __shared__ __align__(16) float As[16][68];
    __shared__ __align__(16) float Bs[16][64];
    const int tid = threadIdx.x;
    const int tx = tid & 15, ty = tid >> 4;
    const int row0 = blockIdx.y * 64, col0 = blockIdx.x * 64;

    float4 pa[2], pb[2];
#pragma unroll
    for (int j = 0; j < 2; j++) {
        int c = tid + j * 128;
        pa[j] = ldf4(A + (size_t)(row0 + (c >> 2)) * 1024 + (c & 3) * 4);
        int kk = c >> 4, nq = c & 15;
        pb[j] = ldf4(W + (size_t)kk * 512 + col0 + nq * 4);
    }
#pragma unroll
    for (int j = 0; j < 2; j++) {
        int c = tid + j * 128;
        int m = c >> 2, kb = (c & 3) * 4;
        As[kb + 0][m] = pa[j].x; As[kb + 1][m] = pa[j].y;
        As[kb + 2][m] = pa[j].z; As[kb + 3][m] = pa[j].w;
        int kk = c >> 4, nq = c & 15;
        *reinterpret_cast<float4*>(&Bs[kk][nq * 4]) = pb[j];
    }
    __syncthreads();

    float acc[8][4];
#pragma unroll
    for (int r = 0; r < 8; r++)
#pragma unroll
        for (int c2 = 0; c2 < 4; c2++) acc[r][c2] = 0.0f;

    for (int k0 = 16;; k0 += 16) {
        const bool more = (k0 < 1024);
        if (more) {
#pragma unroll
            for (int j = 0; j < 2; j++) {
                int c = tid + j * 128;
                pa[j] = ldf4(A + (size_t)(row0 + (c >> 2)) * 1024 + k0 + (c & 3) * 4);
                int kk = c >> 4, nq = c & 15;
                pb[j] = ldf4(W + (size_t)(k0 + kk) * 512 + col0 + nq * 4);
            }
        }
#pragma unroll
        for (int kk = 0; kk < 16; kk++) {
            float4 a0 = ldf4(&As[kk][ty * 8]);
            float4 a1 = ldf4(&As[kk][ty * 8 + 4]);
            float4 b  = ldf4(&Bs[kk][tx * 4]);
            float av[8] = {a0.x, a0.y, a0.z, a0.w, a1.x, a1.y, a1.z, a1.w};
            float bv[4] = {b.x, b.y, b.z, b.w};
#pragma unroll
            for (int r = 0; r < 8; r++)
#pragma unroll
                for (int c2 = 0; c2 < 4; c2++)
                    acc[r][c2] = fmaf(av[r], bv[c2], acc[r][c2]);
        }
        if (!more) break;
        __syncthreads();
#pragma unroll
        for (int j = 0; j < 2; j++) {
            int c = tid + j * 128;
            int m = c >> 2, kb = (c & 3) * 4;
            As[kb + 0][m] = pa[j].x; As[kb + 1][m] = pa[j].y;
            As[kb + 2][m] = pa[j].z; As[kb + 3][m] = pa[j].w;
            int kk = c >> 4, nq = c & 15;
            *reinterpret_cast<float4*>(&Bs[kk][nq * 4]) = pb[j];
        }
        __syncthreads();
    }

    float4 bv4 = ldf4(bias + col0 + tx * 4);
#pragma unroll
    for (int r = 0; r < 8; r++) {
        float4 v = make_float4(acc[r][0] + bv4.x, acc[r][1] + bv4.y,
                               acc[r][2] + bv4.z, acc[r][3] + bv4.w);
        *reinterpret_cast<float4*>(
            Z + (size_t)(row0 + ty * 8 + r) * 512 + col0 + tx * 4) = v;
    }
}

// argmax (first-occurrence tie-break, like jnp.argmax) + logits emission.
__global__ void emit_kernel(const float* __restrict__ logits,
                            float* __restrict__ out, long long out_size)
{
    int row = blockIdx.x;
    int tid = threadIdx.x;
    const float* lr = logits + (size_t)row * 512;

    float best = -3.402823466e38f; int bi = 0;
#pragma unroll
    for (int j = 0; j < 4; j++) {
        int vi = tid + j * 128;
        float v = lr[vi];
        if (v > best) { best = v; bi = vi; }
    }
    __shared__ float sv[128]; __shared__ int si[128];
    sv[tid] = best; si[tid] = bi;
    __syncthreads();
    for (int s = 64; s > 0; s >>= 1) {
        if (tid < s) {
            float v2 = sv[tid + s]; int i2 = si[tid + s];
            if (v2 > sv[tid] || (v2 == sv[tid] && i2 < si[tid])) {
                sv[tid] = v2; si[tid] = i2;
            }
        }
        __syncthreads();
    }
    int amax = si[0];

    if (out_size == BT_LL + BTV_LL) {
        if (tid == 0) out[row] = (float)amax;
        float* lo = out + BT_LL + (size_t)row * 512;
#pragma unroll
        for (int j = 0; j < 4; j++) lo[tid + j * 128] = lr[tid + j * 128];
    } else if (out_size == BTV_LL) {
        float* lo = out + (size_t)row * 512;
#pragma unroll
        for (int j = 0; j < 4; j++) lo[tid + j * 128] = lr[tid + j * 128];
    } else if (out_size == BT_LL) {
        if (tid == 0) reinterpret_cast<int*>(out)[row] = amax;
    } else {
        if (tid == 0 && (long long)row < out_size) out[row] = (float)amax;
#pragma unroll
        for (int j = 0; j < 4; j++) {
            long long o = BT_LL + (long long)row * 512 + tid + j * 128;
            if (o < out_size) out[o] = lr[tid + j * 128];
        }
    }
}

extern "C" void kernel_launch(void* const* d_in, const int* in_sizes, int n_in,
                              void* d_out, int out_size)
{
    Params p;
    p.tokens = (const int*)d_in[0];
    p.emb    = (const float*)d_in[1];
    p.Wx[0] = (const float*)d_in[2];  p.Wh[0] = (const float*)d_in[3];  p.b[0] = (const float*)d_in[4];
    p.Wx[1] = (const float*)d_in[5];  p.Wh[1] = (const float*)d_in[6];  p.b[1] = (const float*)d_in[7];
    p.Wx[2] = (const float*)d_in[8];  p.Wh[2] = (const float*)d_in[9];  p.b[2] = (const float*)d_in[10];
    p.Wx[3] = (const float*)d_in[11]; p.Wh[3] = (const float*)d_in[12]; p.b[3] = (const float*)d_in[13];
    p.Wx[4] = (const float*)d_in[14]; p.Wh[4] = (const float*)d_in[15]; p.b[4] = (const float*)d_in[16];
    p.Wx[5] = (const float*)d_in[17]; p.Wh[5] = (const float*)d_in[18]; p.b[5] = (const float*)d_in[19];
    p.w_mean  = (const float*)d_in[20];
    p.b_mean  = (const float*)d_in[21];
    p.w_sigma = (const float*)d_in[22];
    p.b_sigma = (const float*)d_in[23];
    const float* dec_w = (const float*)d_in[24];
    const float* dec_b = (const float*)d_in[25];
    p.eps = (const float*)d_in[26];

    float *y, *lg;
    cudaGetSymbolAddress((void**)&y,  g_y);
    cudaGetSymbolAddress((void**)&lg, g_logits);

    vae_persistent<<<NBLK, 256>>>(p);
    logits_gemm<<<dim3(8, 512), 128>>>(y, dec_w, dec_b, lg);
    emit_kernel<<<32768, 128>>>(lg, (float*)d_out, (long long)out_size);
}